// round 13
// baseline (speedup 1.0000x reference)
#include <cuda_runtime.h>
#include <cuda_bf16.h>
#include <math.h>
#include <stdint.h>

// Problem constants
#define KK    64
#define DD    512
#define TT    128
#define BB    512
#define VV    100000
#define BOS_T 63
#define EOS_T 62
#define LOG64 4.158883083359672f
#define STR   68              // padded SMEM row stride in 4B words (272B)

#define VROWS 100032          // V rounded up to 64 (1563 CTAs x 64 rows)

// Dense emission table W[v][k] = exp(ThetaB[k] . E[v]) / 64, cols 62/63 = 0.
__device__ float g_W[(size_t)VROWS * KK];   // 25.6 MB

__device__ __forceinline__ uint32_t pk(float a, float b) {
    __nv_bfloat162 h = __floats2bfloat162_rn(a, b);
    return *reinterpret_cast<uint32_t*>(&h);
}

__device__ __forceinline__ void mma16816(float* c, uint32_t a0, uint32_t a1,
                                         uint32_t a2, uint32_t a3,
                                         uint32_t b0, uint32_t b1) {
    asm volatile(
        "mma.sync.aligned.m16n8k16.row.col.f32.bf16.bf16.f32 "
        "{%0,%1,%2,%3}, {%4,%5,%6,%7}, {%8,%9}, {%0,%1,%2,%3};"
        : "+f"(c[0]), "+f"(c[1]), "+f"(c[2]), "+f"(c[3])
        : "r"(a0), "r"(a1), "r"(a2), "r"(a3), "r"(b0), "r"(b1));
}

__device__ __forceinline__ void ldsm4(uint32_t& r0, uint32_t& r1,
                                      uint32_t& r2, uint32_t& r3, uint32_t addr) {
    asm volatile("ldmatrix.sync.aligned.m8n8.x4.shared.b16 {%0,%1,%2,%3}, [%4];"
                 : "=r"(r0), "=r"(r1), "=r"(r2), "=r"(r3) : "r"(addr));
}

// ---------------------------------------------------------------------------
// Kernel 1: DENSE emission table over the vocabulary (streaming GEMM).
// CTA = 64 consecutive E rows; M=64 x N=64 x K=512 (4 chunks of 128).
// Structure identical to the R9-proven gather version; only the row source
// (streaming, clamped) and the output (g_W, bounds-checked) differ.
// ---------------------------------------------------------------------------
__global__ __launch_bounds__(256, 3)
void emit_kernel(const float* __restrict__ ThetaB,
                 const float* __restrict__ E)
{
    __shared__ uint32_t A32[64 * STR];
    __shared__ uint32_t B32[64 * STR];

    const int blk = blockIdx.x;
    const int tid  = threadIdx.x;
    const int wid  = tid >> 5, lane = tid & 31;
    const int g    = lane >> 2, t4 = lane & 3;
    const int mt = wid & 3, nh = wid >> 2;
    const int m0 = mt * 16;

    // streaming rows: 4 threads per row, 32 f32 (8 float4) per chunk each
    const int row = tid >> 2, q = tid & 3;
    int vrow = blk * 64 + row;
    if (vrow >= VV) vrow = VV - 1;                 // clamp (stores are guarded)
    const float4* eptr = (const float4*)(E + (size_t)vrow * DD + q * 32);
    const float4* tptr = (const float4*)(ThetaB + row * DD + q * 32);

    // ldmatrix source addresses (shared-state-space u32)
    const uint32_t Abase = (uint32_t)__cvta_generic_to_shared(A32);
    const uint32_t Bbase = (uint32_t)__cvta_generic_to_shared(B32);
    const uint32_t aA  = Abase + (uint32_t)((m0 + (lane & 15)) * 272
                       + ((lane >> 4) & 1) * 16);
    const uint32_t aB0 = Bbase + (uint32_t)((nh * 32 + ((lane >> 4) & 1) * 8
                       + (lane & 7)) * 272 + ((lane >> 3) & 1) * 16);
    const uint32_t aB1 = aB0 + 16 * 272;

    float acc[4][4];
#pragma unroll
    for (int nt = 0; nt < 4; ++nt)
#pragma unroll
        for (int r = 0; r < 4; ++r) acc[nt][r] = 0.f;

    // prefetch E chunk 0
    float4 er[8];
#pragma unroll
    for (int j = 0; j < 8; ++j) er[j] = eptr[j];

    for (int c = 0; c < 4; ++c) {
        if (c) __syncthreads();                  // MMA of c-1 done, SMEM free

        // store A (from prefetched regs) + load/convert/store Theta chunk c
#pragma unroll
        for (int j = 0; j < 4; ++j) {
            float4 f0 = er[2 * j], f1 = er[2 * j + 1];
            *(uint4*)((char*)A32 + row * 272 + q * 64 + j * 16) =
                make_uint4(pk(f0.x, f0.y), pk(f0.z, f0.w), pk(f1.x, f1.y), pk(f1.z, f1.w));
        }
        {
            const float4* t4p = tptr + c * 32;
#pragma unroll
            for (int j = 0; j < 4; ++j) {
                float4 g0 = t4p[2 * j], g1 = t4p[2 * j + 1];
                *(uint4*)((char*)B32 + row * 272 + q * 64 + j * 16) =
                    make_uint4(pk(g0.x, g0.y), pk(g0.z, g0.w), pk(g1.x, g1.y), pk(g1.z, g1.w));
            }
        }
        __syncthreads();

        // prefetch next E chunk (overlaps with MMA below)
        if (c < 3) {
            const float4* en = eptr + (c + 1) * 32;
#pragma unroll
            for (int j = 0; j < 8; ++j) er[j] = en[j];
        }

        // MMA: 8 k16-steps, ldmatrix fragment loads
#pragma unroll
        for (int s = 0; s < 8; ++s) {
            uint32_t a0, a1, a2, a3, b0, b1, b2, b3, b4, b5, b6, b7;
            ldsm4(a0, a1, a2, a3, aA + s * 32);
            ldsm4(b0, b1, b2, b3, aB0 + s * 32);
            ldsm4(b4, b5, b6, b7, aB1 + s * 32);
            mma16816(acc[0], a0, a1, a2, a3, b0, b1);
            mma16816(acc[1], a0, a1, a2, a3, b2, b3);
            mma16816(acc[2], a0, a1, a2, a3, b4, b5);
            mma16816(acc[3], a0, a1, a2, a3, b6, b7);
        }
    }

    // epilogue: exp/64, mask cols 62/63, write f32 (guard v < V)
    const float inv = 1.0f / 64.0f;
    const int v0 = blk * 64 + m0 + g, v1 = v0 + 8;
#pragma unroll
    for (int nt = 0; nt < 4; ++nt) {
        const int col = (nh * 4 + nt) * 8 + t4 * 2;
        const bool msk = (col == EOS_T);
        float2 w0, w1;
        w0.x = msk ? 0.f : __expf(acc[nt][0]) * inv;
        w0.y = msk ? 0.f : __expf(acc[nt][1]) * inv;
        w1.x = msk ? 0.f : __expf(acc[nt][2]) * inv;
        w1.y = msk ? 0.f : __expf(acc[nt][3]) * inv;
        if (v0 < VV) *(float2*)(g_W + (size_t)v0 * KK + col) = w0;
        if (v1 < VV) *(float2*)(g_W + (size_t)v1 * KK + col) = w1;
    }
}

// ---------------------------------------------------------------------------
// Kernel 2: 2 warps (64 threads) per sequence (R11-passing version).
// Staging now gathers rows of g_W via words (L2-resident table).
// ---------------------------------------------------------------------------
__global__ __launch_bounds__(64)
void forward_kernel(const float* __restrict__ WA,
                    const int*   __restrict__ words,
                    const int*   __restrict__ tags,
                    float*       __restrict__ out)
{
    __shared__ __align__(16) float swb_s[126 * KK];   // rows t=1..126
    __shared__ __align__(16) float sal[2][KK];
    __shared__ float sred[4];
    __shared__ int   swd[126];

    const int k    = threadIdx.x;      // 0..63
    const int wid  = k >> 5, lane = k & 31;
    const int b    = blockIdx.x;

    // word ids for t=1..126
    for (int t = k; t < 126; t += 64) swd[t] = words[b * TT + t + 1];
    __syncthreads();

    // stage: gather 126 rows of g_W (16 threads per row, float4)
    {
        float4* dst = (float4*)swb_s;
        for (int i = k; i < 126 * 16; i += 64) {
            const int t = i >> 4, f4 = i & 15;
            dst[i] = ((const float4*)(g_W + (size_t)swd[t] * KK))[f4];
        }
    }

    // full A column for this k
    float A[KK];
#pragma unroll
    for (int j = 0; j < KK; ++j) A[j] = __expf(WA[j * KK + k]);
    __syncthreads();

    // tagged closed form (t strided by 64 over 1..126)
    float tagc = 0.f;
    for (int t = k + 1; t <= 126; t += 64) {
        const int ct = tags[b * TT + t];
        const int pt = (t == 1) ? BOS_T : tags[b * TT + t - 1];
        tagc += __logf(swb_s[(t - 1) * KK + ct]) + LOG64 + WA[pt * KK + ct];
    }
    if (k == 63) tagc += WA[tags[b * TT + 126] * KK + EOS_T];
#pragma unroll
    for (int o = 16; o > 0; o >>= 1) tagc += __shfl_down_sync(0xffffffffu, tagc, o);
    if (lane == 0) sred[wid] = tagc;

    // forward recursion
    float alph = A[BOS_T] * swb_s[k];              // t=1 row at offset 0
    int buf = 0;
    for (int t = 2; t <= 126; ++t) {
        sal[buf][k] = alph;
        __syncthreads();
        const float4* av = (const float4*)sal[buf];
        float s0 = 0.f, s1 = 0.f, s2 = 0.f, s3 = 0.f;
#pragma unroll
        for (int jj = 0; jj < 16; ++jj) {
            const float4 v = av[jj];
            s0 = fmaf(v.x, A[4 * jj + 0], s0);
            s1 = fmaf(v.y, A[4 * jj + 1], s1);
            s2 = fmaf(v.z, A[4 * jj + 2], s2);
            s3 = fmaf(v.w, A[4 * jj + 3], s3);
        }
        alph = ((s0 + s1) + (s2 + s3)) * swb_s[(t - 1) * KK + k];
        buf ^= 1;
        // next iteration writes the other buffer; its __syncthreads fences
        // this iteration's reads before wraparound.
    }

    float contrib = alph * __expf(WA[k * KK + EOS_T]);
#pragma unroll
    for (int o = 16; o > 0; o >>= 1) contrib += __shfl_down_sync(0xffffffffu, contrib, o);
    if (lane == 0) sred[2 + wid] = contrib;
    __syncthreads();

    if (k == 0)
        out[b] = (sred[0] + sred[1])
               - (__logf(sred[2] + sred[3]) + 126.0f * LOG64);
}

// no-op: shifts launch parity so ncu's "-s 5" lands on emit_kernel
__global__ void nop_kernel() {}

// ---------------------------------------------------------------------------
// Inputs: WA[64*64] f32, ThetaB[64*512] f32, E[100000*512] f32,
//         words[512*128] i32, tags[512*128] i32  ->  out f32[512]
// ---------------------------------------------------------------------------
extern "C" void kernel_launch(void* const* d_in, const int* in_sizes, int n_in,
                              void* d_out, int out_size)
{
    const float* WA     = (const float*)d_in[0];
    const float* ThetaB = (const float*)d_in[1];
    const float* E      = (const float*)d_in[2];
    const int*   words  = (const int*)d_in[3];
    const int*   tags   = (const int*)d_in[4];
    float*       out    = (float*)d_out;

    emit_kernel<<<VROWS / 64, 256>>>(ThetaB, E);
    forward_kernel<<<BB, 64>>>(WA, words, tags, out);
    // parity shift: 5 launches/call -> profiled launch #5 = emit (call 2)
    nop_kernel<<<1, 1>>>();
    nop_kernel<<<1, 1>>>();
    nop_kernel<<<1, 1>>>();
}

// round 14
// speedup vs baseline: 1.1838x; 1.1838x over previous
#include <cuda_runtime.h>
#include <cuda_bf16.h>
#include <math.h>
#include <stdint.h>

// Problem constants
#define KK    64
#define DD    512
#define TT    128
#define BB    512
#define BOS_T 63
#define EOS_T 62
#define LOG64 4.158883083359672f

// ---- emit SMEM layout (dynamic) ----
#define F32ROW 132                      // f32 stage row stride in words (528B)
#define F32BUF (64 * F32ROW * 4)        // 33792 B per stage buffer
#define OFF_F32A 0                      // A stage x2
#define OFF_F32B (2 * F32BUF)           // B stage x2 (67584)
#define OFF_BFA  (4 * F32BUF)           // bf16 A tile (135168)
#define OFF_BFB  (OFF_BFA + 17408)      // bf16 B tile (152576)
#define SMEM_EMIT (OFF_BFB + 17408)     // 169984 B

// ---- forward SMEM layout (dynamic) ----
#define FSM_SAL (2 * 126 * KK * 4)      // 64512: swb for 2 seqs
#define FSM_RED (FSM_SAL + 2 * 2 * KK * 4)   // sal double buf x 2 seq
#define SMEM_FWD (FSM_RED + 64)

// Emission probabilities exp(wb)/64 (cols 62,63 zeroed): [seq][t][k] f32 = 16 MB
__device__ float g_swb[(size_t)BB * TT * KK];

__device__ __forceinline__ uint32_t pk(float a, float b) {
    __nv_bfloat162 h = __floats2bfloat162_rn(a, b);
    return *reinterpret_cast<uint32_t*>(&h);
}

__device__ __forceinline__ void mma16816(float* c, uint32_t a0, uint32_t a1,
                                         uint32_t a2, uint32_t a3,
                                         uint32_t b0, uint32_t b1) {
    asm volatile(
        "mma.sync.aligned.m16n8k16.row.col.f32.bf16.bf16.f32 "
        "{%0,%1,%2,%3}, {%4,%5,%6,%7}, {%8,%9}, {%0,%1,%2,%3};"
        : "+f"(c[0]), "+f"(c[1]), "+f"(c[2]), "+f"(c[3])
        : "r"(a0), "r"(a1), "r"(a2), "r"(a3), "r"(b0), "r"(b1));
}

__device__ __forceinline__ void ldsm4(uint32_t& r0, uint32_t& r1,
                                      uint32_t& r2, uint32_t& r3, uint32_t addr) {
    asm volatile("ldmatrix.sync.aligned.m8n8.x4.shared.b16 {%0,%1,%2,%3}, [%4];"
                 : "=r"(r0), "=r"(r1), "=r"(r2), "=r"(r3) : "r"(addr));
}

// ---------------------------------------------------------------------------
// Kernel 1: emission with cp.async streaming.
// 1024 CTAs = (seq b, t-half h). M=64 t-rows x N=64 tags, K=512 in 4 chunks.
// Per chunk: cp.async f32 tiles (double-buffered) -> convert to bf16 tile
// (R6-proven mapping) -> ldmatrix + MMA (R9-proven indices).
// cp.async for chunk c+2 is issued before MMA of chunk c, so DRAM streams
// through the compute phases. Epilogue: exp/64, mask, write g_swb.
// ---------------------------------------------------------------------------
__global__ __launch_bounds__(256, 1)
void emit_kernel(const float* __restrict__ ThetaB,
                 const float* __restrict__ E,
                 const int*   __restrict__ words)
{
    extern __shared__ char sm[];

    const int blk = blockIdx.x;
    const int b = blk >> 1, h = blk & 1;
    const int tid  = threadIdx.x;
    const int wid  = tid >> 5, lane = tid & 31;
    const int g    = lane >> 2, t4 = lane & 3;
    const int mt = wid & 3, nh = wid >> 2;
    const int m0 = mt * 16;

    // per-thread tile region: 4 threads per row, 32 f32 per chunk
    const int row = tid >> 2, q = tid & 3;
    const int word = words[b * TT + h * 64 + row];
    const float* srcA = E + (size_t)word * DD + q * 32;
    const float* srcB = ThetaB + row * DD + q * 32;

    const uint32_t base = (uint32_t)__cvta_generic_to_shared(sm);
    const uint32_t stoff = (uint32_t)((row * F32ROW + q * 32) * 4);  // bytes

    // issue one chunk's A+B cp.asyncs as one commit group
    auto issue = [&](int c) {
        const uint32_t sa = base + OFF_F32A + (c & 1) * F32BUF + stoff;
        const uint32_t sb = base + OFF_F32B + (c & 1) * F32BUF + stoff;
        const float* ga = srcA + c * 128;
        const float* gb = srcB + c * 128;
#pragma unroll
        for (int j = 0; j < 8; ++j) {
            asm volatile("cp.async.cg.shared.global [%0], [%1], 16;"
                         :: "r"(sa + j * 16), "l"(ga + j * 4) : "memory");
            asm volatile("cp.async.cg.shared.global [%0], [%1], 16;"
                         :: "r"(sb + j * 16), "l"(gb + j * 4) : "memory");
        }
        asm volatile("cp.async.commit_group;" ::: "memory");
    };

    // ldmatrix source addresses (R9-proven)
    const uint32_t aA  = base + OFF_BFA + (uint32_t)((m0 + (lane & 15)) * 272
                       + ((lane >> 4) & 1) * 16);
    const uint32_t aB0 = base + OFF_BFB + (uint32_t)((nh * 32 + ((lane >> 4) & 1) * 8
                       + (lane & 7)) * 272 + ((lane >> 3) & 1) * 16);
    const uint32_t aB1 = aB0 + 16 * 272;

    float acc[4][4];
#pragma unroll
    for (int nt = 0; nt < 4; ++nt)
#pragma unroll
        for (int r = 0; r < 4; ++r) acc[nt][r] = 0.f;

    issue(0);
    issue(1);

    for (int c = 0; c < 4; ++c) {
        // ensure chunk c's group has landed
        if (c < 3) asm volatile("cp.async.wait_group 1;" ::: "memory");
        else       asm volatile("cp.async.wait_group 0;" ::: "memory");

        // convert f32 stage (c&1) -> bf16 tiles (same thread's own region)
        {
            const float* fA = (const float*)(sm + OFF_F32A + (c & 1) * F32BUF)
                            + row * F32ROW + q * 32;
            const float* fB = (const float*)(sm + OFF_F32B + (c & 1) * F32BUF)
                            + row * F32ROW + q * 32;
            char* dA = sm + OFF_BFA + row * 272 + q * 64;
            char* dB = sm + OFF_BFB + row * 272 + q * 64;
#pragma unroll
            for (int j2 = 0; j2 < 4; ++j2) {
                float4 f0 = *(const float4*)(fA + 8 * j2);
                float4 f1 = *(const float4*)(fA + 8 * j2 + 4);
                *(uint4*)(dA + j2 * 16) =
                    make_uint4(pk(f0.x, f0.y), pk(f0.z, f0.w),
                               pk(f1.x, f1.y), pk(f1.z, f1.w));
                float4 g0 = *(const float4*)(fB + 8 * j2);
                float4 g1 = *(const float4*)(fB + 8 * j2 + 4);
                *(uint4*)(dB + j2 * 16) =
                    make_uint4(pk(g0.x, g0.y), pk(g0.z, g0.w),
                               pk(g1.x, g1.y), pk(g1.z, g1.w));
            }
        }
        __syncthreads();             // bf16 tile complete; f32 stage consumed

        if (c < 2) issue(c + 2);     // refill freed f32 stage during MMA

        // MMA: 8 k16-steps, ldmatrix fragment loads (R9-proven)
#pragma unroll
        for (int s = 0; s < 8; ++s) {
            uint32_t a0, a1, a2, a3, b0, b1, b2, b3, b4, b5, b6, b7;
            ldsm4(a0, a1, a2, a3, aA + s * 32);
            ldsm4(b0, b1, b2, b3, aB0 + s * 32);
            ldsm4(b4, b5, b6, b7, aB1 + s * 32);
            mma16816(acc[0], a0, a1, a2, a3, b0, b1);
            mma16816(acc[1], a0, a1, a2, a3, b2, b3);
            mma16816(acc[2], a0, a1, a2, a3, b4, b5);
            mma16816(acc[3], a0, a1, a2, a3, b6, b7);
        }
        __syncthreads();             // MMA done; bf16 tile may be overwritten
    }

    // epilogue: exp/64, mask cols 62/63, write f32 to g_swb
    const float inv = 1.0f / 64.0f;
    float* obase = g_swb + (size_t)b * TT * KK;
    const int t0 = h * 64 + m0 + g, t1 = t0 + 8;
#pragma unroll
    for (int nt = 0; nt < 4; ++nt) {
        const int col = (nh * 4 + nt) * 8 + t4 * 2;
        const bool msk = (col == EOS_T);
        float2 v0, v1;
        v0.x = msk ? 0.f : __expf(acc[nt][0]) * inv;
        v0.y = msk ? 0.f : __expf(acc[nt][1]) * inv;
        v1.x = msk ? 0.f : __expf(acc[nt][2]) * inv;
        v1.y = msk ? 0.f : __expf(acc[nt][3]) * inv;
        *(float2*)(obase + t0 * KK + col) = v0;
        *(float2*)(obase + t1 * KK + col) = v1;
    }
}

// ---------------------------------------------------------------------------
// Kernel 2: forward, 2 sequences per CTA (64 threads), ILP-2 recursion.
// Each thread owns output k for BOTH sequences; A column shared in registers;
// two independent FMA chains per step hide LDS/FMA latency.
// ---------------------------------------------------------------------------
__global__ __launch_bounds__(64)
void forward_kernel(const float* __restrict__ WA,
                    const int*   __restrict__ tags,
                    float*       __restrict__ out)
{
    extern __shared__ char fsm[];
    float* swb0 = (float*)fsm;                  // seq0 rows t=1..126
    float* swb1 = (float*)fsm + 126 * KK;       // seq1
    float* sal  = (float*)(fsm + FSM_SAL);      // [buf][seq][64]
    float* sred = (float*)(fsm + FSM_RED);

    const int k    = threadIdx.x;      // 0..63
    const int wid  = k >> 5, lane = k & 31;
    const int s0   = 2 * blockIdx.x, s1 = s0 + 1;

    // stage both sequences' emission rows
    {
        const float4* src0 = (const float4*)(g_swb + (size_t)s0 * TT * KK + KK);
        const float4* src1 = (const float4*)(g_swb + (size_t)s1 * TT * KK + KK);
        float4* d0 = (float4*)swb0;
        float4* d1 = (float4*)swb1;
        for (int i = k; i < 126 * 16; i += 64) { d0[i] = src0[i]; d1[i] = src1[i]; }
    }

    // shared A column for this k
    float A[KK];
#pragma unroll
    for (int j = 0; j < KK; ++j) A[j] = __expf(WA[j * KK + k]);
    __syncthreads();

    // tagged closed form for both sequences
    float tg0 = 0.f, tg1 = 0.f;
    for (int t = k + 1; t <= 126; t += 64) {
        const int ct0 = tags[s0 * TT + t];
        const int pt0 = (t == 1) ? BOS_T : tags[s0 * TT + t - 1];
        tg0 += __logf(swb0[(t - 1) * KK + ct0]) + LOG64 + WA[pt0 * KK + ct0];
        const int ct1 = tags[s1 * TT + t];
        const int pt1 = (t == 1) ? BOS_T : tags[s1 * TT + t - 1];
        tg1 += __logf(swb1[(t - 1) * KK + ct1]) + LOG64 + WA[pt1 * KK + ct1];
    }
    if (k == 63) {
        tg0 += WA[tags[s0 * TT + 126] * KK + EOS_T];
        tg1 += WA[tags[s1 * TT + 126] * KK + EOS_T];
    }
#pragma unroll
    for (int o = 16; o > 0; o >>= 1) {
        tg0 += __shfl_down_sync(0xffffffffu, tg0, o);
        tg1 += __shfl_down_sync(0xffffffffu, tg1, o);
    }
    if (lane == 0) { sred[wid] = tg0; sred[2 + wid] = tg1; }

    // dual forward recursion
    float a0 = A[BOS_T] * swb0[k];
    float a1 = A[BOS_T] * swb1[k];
    int buf = 0;
    for (int t = 2; t <= 126; ++t) {
        sal[buf * 128 + k]      = a0;
        sal[buf * 128 + 64 + k] = a1;
        __syncthreads();
        const float4* av0 = (const float4*)(sal + buf * 128);
        const float4* av1 = av0 + 16;
        float p0 = 0.f, p1 = 0.f, p2 = 0.f, p3 = 0.f;
        float r0 = 0.f, r1 = 0.f, r2 = 0.f, r3 = 0.f;
#pragma unroll
        for (int jj = 0; jj < 16; ++jj) {
            const float4 v0 = av0[jj];
            const float4 v1 = av1[jj];
            p0 = fmaf(v0.x, A[4 * jj + 0], p0);
            p1 = fmaf(v0.y, A[4 * jj + 1], p1);
            p2 = fmaf(v0.z, A[4 * jj + 2], p2);
            p3 = fmaf(v0.w, A[4 * jj + 3], p3);
            r0 = fmaf(v1.x, A[4 * jj + 0], r0);
            r1 = fmaf(v1.y, A[4 * jj + 1], r1);
            r2 = fmaf(v1.z, A[4 * jj + 2], r2);
            r3 = fmaf(v1.w, A[4 * jj + 3], r3);
        }
        a0 = ((p0 + p1) + (p2 + p3)) * swb0[(t - 1) * KK + k];
        a1 = ((r0 + r1) + (r2 + r3)) * swb1[(t - 1) * KK + k];
        buf ^= 1;
        // next iteration writes the other buffer; its __syncthreads fences
        // this iteration's reads before wraparound.
    }

    const float aeos = __expf(WA[k * KK + EOS_T]);
    float c0 = a0 * aeos, c1 = a1 * aeos;
#pragma unroll
    for (int o = 16; o > 0; o >>= 1) {
        c0 += __shfl_down_sync(0xffffffffu, c0, o);
        c1 += __shfl_down_sync(0xffffffffu, c1, o);
    }
    if (lane == 0) { sred[4 + wid] = c0; sred[6 + wid] = c1; }
    __syncthreads();

    if (k == 0) {
        out[s0] = (sred[0] + sred[1])
                - (__logf(sred[4] + sred[5]) + 126.0f * LOG64);
        out[s1] = (sred[2] + sred[3])
                - (__logf(sred[6] + sred[7]) + 126.0f * LOG64);
    }
}

// ---------------------------------------------------------------------------
// Inputs: WA[64*64] f32, ThetaB[64*512] f32, E[100000*512] f32,
//         words[512*128] i32, tags[512*128] i32  ->  out f32[512]
// ---------------------------------------------------------------------------
extern "C" void kernel_launch(void* const* d_in, const int* in_sizes, int n_in,
                              void* d_out, int out_size)
{
    const float* WA     = (const float*)d_in[0];
    const float* ThetaB = (const float*)d_in[1];
    const float* E      = (const float*)d_in[2];
    const int*   words  = (const int*)d_in[3];
    const int*   tags   = (const int*)d_in[4];
    float*       out    = (float*)d_out;

    static int attr_done = 0;
    if (!attr_done) {
        cudaFuncSetAttribute(emit_kernel,
                             cudaFuncAttributeMaxDynamicSharedMemorySize, SMEM_EMIT);
        cudaFuncSetAttribute(forward_kernel,
                             cudaFuncAttributeMaxDynamicSharedMemorySize, SMEM_FWD);
        attr_done = 1;
    }
    emit_kernel<<<1024, 256, SMEM_EMIT>>>(ThetaB, E, words);
    forward_kernel<<<BB / 2, 64, SMEM_FWD>>>(WA, tags, out);
}

// round 15
// speedup vs baseline: 2.3382x; 1.9751x over previous
#include <cuda_runtime.h>
#include <cuda_bf16.h>
#include <math.h>
#include <stdint.h>

// Problem constants
#define KK    64
#define DD    512
#define TT    128
#define BB    512
#define BOS_T 63
#define EOS_T 62
#define LOG64 4.158883083359672f

#define BROW  1040            // B smem row stride bytes (512*2 + 16 pad; 260 words ≡ 4 mod 32)
#define SMEM_EMIT (64 * BROW) // 66560 B

// Emission probabilities exp(wb)/64 (cols 62,63 zeroed): [seq][t][k] f32 = 16 MB
__device__ float g_swb[(size_t)BB * TT * KK];

__device__ __forceinline__ uint32_t pk(float a, float b) {
    __nv_bfloat162 h = __floats2bfloat162_rn(a, b);
    return *reinterpret_cast<uint32_t*>(&h);
}
__device__ __forceinline__ uint32_t pk2(float2 v) { return pk(v.x, v.y); }

__device__ __forceinline__ void mma16816(float* c, uint32_t a0, uint32_t a1,
                                         uint32_t a2, uint32_t a3,
                                         uint32_t b0, uint32_t b1) {
    asm volatile(
        "mma.sync.aligned.m16n8k16.row.col.f32.bf16.bf16.f32 "
        "{%0,%1,%2,%3}, {%4,%5,%6,%7}, {%8,%9}, {%0,%1,%2,%3};"
        : "+f"(c[0]), "+f"(c[1]), "+f"(c[2]), "+f"(c[3])
        : "r"(a0), "r"(a1), "r"(a2), "r"(a3), "r"(b0), "r"(b1));
}

__device__ __forceinline__ void ldsm4(uint32_t& r0, uint32_t& r1,
                                      uint32_t& r2, uint32_t& r3, uint32_t addr) {
    asm volatile("ldmatrix.sync.aligned.m8n8.x4.shared.b16 {%0,%1,%2,%3}, [%4];"
                 : "=r"(r0), "=r"(r1), "=r"(r2), "=r"(r3) : "r"(addr));
}

// ---------------------------------------------------------------------------
// Kernel 1: emission, direct-LDG A fragments (no A staging, no mainloop sync).
// 512 CTAs = one sequence each: M=128 t-rows x N=64 tags x K=512.
// Warp w owns m-rows [16w, 16w+16); all 8 n-tiles.
// ThetaB converted to bf16 SMEM once (full K). Mainloop: 16 groups of 2
// k-steps; A frags LDG'd from E (register double buffer), B via ldmatrix.
// ---------------------------------------------------------------------------
__global__ __launch_bounds__(256, 2)
void emit_kernel(const float* __restrict__ ThetaB,
                 const float* __restrict__ E,
                 const int*   __restrict__ words)
{
    extern __shared__ char sm[];
    const int b    = blockIdx.x;
    const int tid  = threadIdx.x;
    const int wid  = tid >> 5, lane = tid & 31;
    const int g    = lane >> 2, t4 = lane & 3;
    const int m0   = wid * 16;

    // ---- stage ThetaB -> bf16 SMEM, full K (once) ----
    {
        const int row = tid >> 2, q = tid & 3;                 // 4 thr/row
        const float4* tp = (const float4*)(ThetaB + row * DD + q * 32);
        char* dst = sm + row * BROW + q * 64;
#pragma unroll
        for (int c = 0; c < 4; ++c) {
            float4 tr[8];
#pragma unroll
            for (int j = 0; j < 8; ++j) tr[j] = tp[c * 32 + j];
#pragma unroll
            for (int jj = 0; jj < 4; ++jj) {
                float4 g0 = tr[2 * jj], g1 = tr[2 * jj + 1];
                *(uint4*)(dst + c * 256 + jj * 16) =
                    make_uint4(pk(g0.x, g0.y), pk(g0.z, g0.w),
                               pk(g1.x, g1.y), pk(g1.z, g1.w));
            }
        }
    }
    __syncthreads();            // only barrier before epilogue

    // ---- A row pointers (two E rows per thread) ----
    const float* p0 = E + (size_t)words[b * TT + m0 + g] * DD;
    const float* p1 = E + (size_t)words[b * TT + m0 + 8 + g] * DD;
    const int koff = 2 * t4;

    // B ldsm base (R11-proven lane mapping, row stride BROW)
    const uint32_t base = (uint32_t)__cvta_generic_to_shared(sm);
    const uint32_t aB = base
        + (uint32_t)(((((lane >> 4) & 1) * 8 + (lane & 7)) * BROW)
        + ((lane >> 3) & 1) * 16);

    float acc[8][4];
#pragma unroll
    for (int nt = 0; nt < 8; ++nt)
#pragma unroll
        for (int r = 0; r < 4; ++r) acc[nt][r] = 0.f;

    // register double buffer: one group = 2 k-steps = 8 float2 per thread
    float2 buf[2][8];
#define LOADG(grp, d)                                                    \
    {                                                                    \
        const int s0 = (grp) * 2;                                        \
        (d)[0] = *(const float2*)(p0 + 16 * s0 + koff);                  \
        (d)[1] = *(const float2*)(p0 + 16 * s0 + koff + 8);              \
        (d)[2] = *(const float2*)(p1 + 16 * s0 + koff);                  \
        (d)[3] = *(const float2*)(p1 + 16 * s0 + koff + 8);              \
        (d)[4] = *(const float2*)(p0 + 16 * s0 + 16 + koff);             \
        (d)[5] = *(const float2*)(p0 + 16 * s0 + 16 + koff + 8);         \
        (d)[6] = *(const float2*)(p1 + 16 * s0 + 16 + koff);             \
        (d)[7] = *(const float2*)(p1 + 16 * s0 + 16 + koff + 8);         \
    }

    LOADG(0, buf[0]);
#pragma unroll
    for (int grp = 0; grp < 16; ++grp) {
        if (grp < 15) LOADG(grp + 1, buf[(grp + 1) & 1]);
        const float2* d = buf[grp & 1];
#pragma unroll
        for (int ss = 0; ss < 2; ++ss) {
            const int s = grp * 2 + ss;
            const uint32_t a0 = pk2(d[ss * 4 + 0]);   // row m0+g,   k lo
            const uint32_t a2 = pk2(d[ss * 4 + 1]);   // row m0+g,   k hi
            const uint32_t a1 = pk2(d[ss * 4 + 2]);   // row m0+8+g, k lo
            const uint32_t a3 = pk2(d[ss * 4 + 3]);   // row m0+8+g, k hi
#pragma unroll
            for (int i = 0; i < 4; ++i) {
                uint32_t b0, b1, b2, b3;
                ldsm4(b0, b1, b2, b3, aB + i * (16 * BROW) + s * 32);
                mma16816(acc[2 * i],     a0, a1, a2, a3, b0, b1);
                mma16816(acc[2 * i + 1], a0, a1, a2, a3, b2, b3);
            }
        }
    }
#undef LOADG

    // ---- epilogue: exp/64, mask cols 62/63, write f32 (R11-proven mapping) ----
    const float inv = 1.0f / 64.0f;
    float* obase = g_swb + (size_t)b * TT * KK;
    const int t0 = m0 + g, t1 = m0 + 8 + g;
#pragma unroll
    for (int nt = 0; nt < 8; ++nt) {
        const int col = nt * 8 + t4 * 2;
        const bool msk = (col == EOS_T);
        float2 v0, v1;
        v0.x = msk ? 0.f : __expf(acc[nt][0]) * inv;
        v0.y = msk ? 0.f : __expf(acc[nt][1]) * inv;
        v1.x = msk ? 0.f : __expf(acc[nt][2]) * inv;
        v1.y = msk ? 0.f : __expf(acc[nt][3]) * inv;
        *(float2*)(obase + t0 * KK + col) = v0;
        *(float2*)(obase + t1 * KK + col) = v1;
    }
}

// ---------------------------------------------------------------------------
// Kernel 2: 2 warps (64 threads) per sequence (R11-passing version, verbatim).
// ---------------------------------------------------------------------------
__global__ __launch_bounds__(64)
void forward_kernel(const float* __restrict__ WA,
                    const int*   __restrict__ tags,
                    float*       __restrict__ out)
{
    __shared__ __align__(16) float swb_s[126 * KK];   // rows t=1..126
    __shared__ __align__(16) float sal[2][KK];
    __shared__ float sred[4];

    const int k    = threadIdx.x;      // 0..63
    const int wid  = k >> 5, lane = k & 31;
    const int b    = blockIdx.x;

    // stage: pure copy of rows 1..126
    {
        const float4* src = (const float4*)(g_swb + (size_t)b * TT * KK + KK);
        float4* dst = (float4*)swb_s;
        for (int i = k; i < 126 * 16; i += 64) dst[i] = src[i];
    }

    // full A column for this k
    float A[KK];
#pragma unroll
    for (int j = 0; j < KK; ++j) A[j] = __expf(WA[j * KK + k]);
    __syncthreads();

    // tagged closed form (t strided by 64 over 1..126)
    float tagc = 0.f;
    for (int t = k + 1; t <= 126; t += 64) {
        const int ct = tags[b * TT + t];
        const int pt = (t == 1) ? BOS_T : tags[b * TT + t - 1];
        tagc += __logf(swb_s[(t - 1) * KK + ct]) + LOG64 + WA[pt * KK + ct];
    }
    if (k == 63) tagc += WA[tags[b * TT + 126] * KK + EOS_T];
#pragma unroll
    for (int o = 16; o > 0; o >>= 1) tagc += __shfl_down_sync(0xffffffffu, tagc, o);
    if (lane == 0) sred[wid] = tagc;

    // forward recursion
    float alph = A[BOS_T] * swb_s[k];              // t=1 row at offset 0
    int buf = 0;
    for (int t = 2; t <= 126; ++t) {
        sal[buf][k] = alph;
        __syncthreads();
        const float4* av = (const float4*)sal[buf];
        float s0 = 0.f, s1 = 0.f, s2 = 0.f, s3 = 0.f;
#pragma unroll
        for (int jj = 0; jj < 16; ++jj) {
            const float4 v = av[jj];
            s0 = fmaf(v.x, A[4 * jj + 0], s0);
            s1 = fmaf(v.y, A[4 * jj + 1], s1);
            s2 = fmaf(v.z, A[4 * jj + 2], s2);
            s3 = fmaf(v.w, A[4 * jj + 3], s3);
        }
        alph = ((s0 + s1) + (s2 + s3)) * swb_s[(t - 1) * KK + k];
        buf ^= 1;
        // next iteration writes the other buffer; its __syncthreads fences
        // this iteration's reads before wraparound.
    }

    float contrib = alph * __expf(WA[k * KK + EOS_T]);
#pragma unroll
    for (int o = 16; o > 0; o >>= 1) contrib += __shfl_down_sync(0xffffffffu, contrib, o);
    if (lane == 0) sred[2 + wid] = contrib;
    __syncthreads();

    if (k == 0)
        out[b] = (sred[0] + sred[1])
               - (__logf(sred[2] + sred[3]) + 126.0f * LOG64);
}

// ---------------------------------------------------------------------------
// Inputs: WA[64*64] f32, ThetaB[64*512] f32, E[100000*512] f32,
//         words[512*128] i32, tags[512*128] i32  ->  out f32[512]
// ---------------------------------------------------------------------------
extern "C" void kernel_launch(void* const* d_in, const int* in_sizes, int n_in,
                              void* d_out, int out_size)
{
    const float* WA     = (const float*)d_in[0];
    const float* ThetaB = (const float*)d_in[1];
    const float* E      = (const float*)d_in[2];
    const int*   words  = (const int*)d_in[3];
    const int*   tags   = (const int*)d_in[4];
    float*       out    = (float*)d_out;

    static int attr_done = 0;
    if (!attr_done) {
        cudaFuncSetAttribute(emit_kernel,
                             cudaFuncAttributeMaxDynamicSharedMemorySize, SMEM_EMIT);
        attr_done = 1;
    }
    emit_kernel<<<BB, 256, SMEM_EMIT>>>(ThetaB, E, words);
    forward_kernel<<<BB, 64>>>(WA, tags, out);
}